// round 1
// baseline (speedup 1.0000x reference)
#include <cuda_runtime.h>
#include <cuda_bf16.h>
#include <math.h>

#define BATCH 4
#define SEQ 6007
#define HID 1536
#define NH 8
#define HD 192
#define CHUNK 12
#define MAX_PAST 12
#define CTX 24
#define PL 13
#define NB 501
#define SP (NB * CHUNK)
#define MTOT (BATCH * SEQ)
#define MPAD (BATCH * SP)
#define SOFTCAP 50.0f

__device__ float g_q[(size_t)MPAD * HID];
__device__ float g_k[(size_t)MPAD * HID];
__device__ float g_v[(size_t)MPAD * HID];
__device__ float g_att[(size_t)MPAD * HID];
__device__ float g_rel[PL * HID];
__device__ float g_qscale[HD];

__device__ __forceinline__ int prow(int m) {
    int b = m / SEQ;
    return b * SP + (m - b * SEQ);
}

__global__ void prep_qscale(const float* __restrict__ pds) {
    int d = threadIdx.x;
    if (d < HD) {
        float x = pds[d];
        float sp = (x > 20.f) ? x : log1pf(expf(x));
        const float qsc = (1.0f / sqrtf((float)HD)) * 1.4426950408889634f;
        g_qscale[d] = qsc * sp;
    }
}

__global__ void relgemm(const float* __restrict__ P, const float* __restrict__ W) {
    int n = blockIdx.x * 128 + threadIdx.x;
    float acc[PL];
#pragma unroll
    for (int p = 0; p < PL; p++) acc[p] = 0.f;
    for (int k = 0; k < HID; k++) {
        float w = W[(size_t)k * HID + n];
#pragma unroll
        for (int p = 0; p < PL; p++) acc[p] = fmaf(P[p * HID + k], w, acc[p]);
    }
#pragma unroll
    for (int p = 0; p < PL; p++) g_rel[p * HID + n] = acc[p];
}

#define BM 128
#define BN 128
#define BK 8
#define TM 8
#define TN 8

// MODE 0: {g_q,g_k,g_v}[padded] = X @ {Wq,Wk,Wv}; z==0 scaled by g_qscale.
// MODE 1: Out[contig] = g_att[padded] @ W0.
template <int MODE>
__global__ void sgemm(const float* __restrict__ Ain,
                      const float* __restrict__ W0,
                      const float* __restrict__ W1,
                      const float* __restrict__ W2,
                      float* __restrict__ Out) {
    const int z = blockIdx.z;
    const float* W = (MODE == 1) ? W0 : (z == 0 ? W0 : (z == 1 ? W1 : W2));

    const int n0 = blockIdx.x * BN;
    const int m0 = blockIdx.y * BM;

    __shared__ float As[BK][BM];
    __shared__ float Bs[BK][BN];

    const int tid = threadIdx.x;
    const int arow = tid >> 1;
    const int acol = (tid & 1) * 4;
    const int am = m0 + arow;
    const bool aval = (am < MTOT);
    const float* Aptr;
    if (MODE == 0) {
        Aptr = Ain + (size_t)am * HID + acol;
    } else {
        Aptr = g_att + (size_t)(aval ? prow(am) : 0) * HID + acol;
    }
    const int brow = tid >> 5;
    const int bcol = (tid & 31) * 4;
    const float* Bptr = W + (size_t)brow * HID + n0 + bcol;

    const int tx = tid & 15;
    const int ty = tid >> 4;

    float acc[TM][TN];
#pragma unroll
    for (int i = 0; i < TM; i++)
#pragma unroll
        for (int j = 0; j < TN; j++) acc[i][j] = 0.f;

    for (int k0 = 0; k0 < HID; k0 += BK) {
        float4 av = aval ? *(const float4*)(Aptr + k0)
                         : make_float4(0.f, 0.f, 0.f, 0.f);
        float4 bv = *(const float4*)(Bptr + (size_t)k0 * HID);
        __syncthreads();
        As[acol + 0][arow] = av.x;
        As[acol + 1][arow] = av.y;
        As[acol + 2][arow] = av.z;
        As[acol + 3][arow] = av.w;
        *(float4*)&Bs[brow][bcol] = bv;
        __syncthreads();
#pragma unroll
        for (int kk = 0; kk < BK; kk++) {
            float a[TM], b[TN];
            float4 a0 = *(const float4*)&As[kk][ty * TM];
            float4 a1 = *(const float4*)&As[kk][ty * TM + 4];
            a[0] = a0.x; a[1] = a0.y; a[2] = a0.z; a[3] = a0.w;
            a[4] = a1.x; a[5] = a1.y; a[6] = a1.z; a[7] = a1.w;
            float4 b0 = *(const float4*)&Bs[kk][tx * TN];
            float4 b1 = *(const float4*)&Bs[kk][tx * TN + 4];
            b[0] = b0.x; b[1] = b0.y; b[2] = b0.z; b[3] = b0.w;
            b[4] = b1.x; b[5] = b1.y; b[6] = b1.z; b[7] = b1.w;
#pragma unroll
            for (int i = 0; i < TM; i++)
#pragma unroll
                for (int j = 0; j < TN; j++) acc[i][j] = fmaf(a[i], b[j], acc[i][j]);
        }
    }

    float cscale[TN];
#pragma unroll
    for (int j = 0; j < TN; j++)
        cscale[j] = (MODE == 0 && z == 0) ? g_qscale[(n0 + tx * TN + j) % HD] : 1.f;

    float* O;
    if (MODE == 0) O = (z == 0 ? g_q : (z == 1 ? g_k : g_v));
    else O = Out;

#pragma unroll
    for (int i = 0; i < TM; i++) {
        int m = m0 + ty * TM + i;
        if (m >= MTOT) continue;
        size_t row = (MODE == 0) ? (size_t)prow(m) : (size_t)m;
        float* orow = O + row * HID + n0 + tx * TN;
#pragma unroll
        for (int j = 0; j < TN; j++) orow[j] = acc[i][j] * cscale[j];
    }
}

#define ALD 193

__global__ void attn_kernel() {
    extern __shared__ float sm[];
    float* qs = sm;
    float* ks = qs + CHUNK * ALD;
    float* vs = ks + CTX * ALD;
    float* rs = vs + CTX * ALD;
    float* sc = rs + PL * ALD;

    const int n = blockIdx.x;
    const int h = blockIdx.y;
    const int b = blockIdx.z;
    const int tid = threadIdx.x;

    const int base = b * SP + n * CHUNK;
    const size_t hoff = (size_t)h * HD;

    for (int e = tid; e < CHUNK * HD; e += 256) {
        int r = e / HD, d = e - r * HD;
        qs[r * ALD + d] = g_q[(size_t)(base + r) * HID + hoff + d];
    }
    for (int e = tid; e < CTX * HD; e += 256) {
        int r = e / HD, d = e - r * HD;
        int srow = base - MAX_PAST + r;
        float kk = 0.f, vv = 0.f;
        if (srow >= b * SP) {
            size_t off = (size_t)srow * HID + hoff + d;
            kk = g_k[off];
            vv = g_v[off];
        }
        ks[r * ALD + d] = kk;
        vs[r * ALD + d] = vv;
    }
    for (int e = tid; e < PL * HD; e += 256) {
        int p = e / HD, d = e - p * HD;
        rs[p * ALD + d] = g_rel[p * HID + hoff + d];
    }
    __syncthreads();

    for (int e = tid; e < CHUNK * CTX; e += 256) {
        int qi = e / CTX, c = e - qi * CTX;
        int absq = n * CHUNK + qi;
        int absk = n * CHUNK - MAX_PAST + c;
        bool valid = (absq < SEQ) && (absk >= 0) && (absk < SEQ) &&
                     (c > qi) && (c <= qi + MAX_PAST);
        float val = -1e9f;
        if (valid) {
            const float* qr = qs + qi * ALD;
            const float* kr = ks + c * ALD;
            const float* rr = rs + (c - qi) * ALD;
            float ac = 0.f, bd = 0.f;
#pragma unroll 8
            for (int d = 0; d < HD; d++) {
                float qv = qr[d];
                ac = fmaf(qv, kr[d], ac);
                bd = fmaf(qv, rr[d], bd);
            }
            float w = ac + bd;
            val = tanhf(w * (1.0f / SOFTCAP)) * SOFTCAP;
        }
        sc[e] = val;
    }
    __syncthreads();

    if (tid < CHUNK) {
        float* row = sc + tid * CTX;
        float mx = -1e30f;
#pragma unroll
        for (int c = 0; c < CTX; c++) mx = fmaxf(mx, row[c]);
        float s = 0.f;
#pragma unroll
        for (int c = 0; c < CTX; c++) {
            float e2 = __expf(row[c] - mx);
            row[c] = e2;
            s += e2;
        }
        float inv = 1.f / s;
#pragma unroll
        for (int c = 0; c < CTX; c++) row[c] *= inv;
    }
    __syncthreads();

    for (int e = tid; e < CHUNK * HD; e += 256) {
        int qi = e / HD, d = e - qi * HD;
        const float* pr = sc + qi * CTX;
        float acc = 0.f;
#pragma unroll
        for (int c = 0; c < CTX; c++) acc = fmaf(pr[c], vs[c * ALD + d], acc);
        g_att[(size_t)(base + qi) * HID + hoff + d] = acc;
    }
}

extern "C" void kernel_launch(void* const* d_in, const int* in_sizes, int n_in,
                              void* d_out, int out_size) {
    const float* x     = (const float*)d_in[0];
    const float* pe    = (const float*)d_in[1];
    const float* Wq    = (const float*)d_in[2];
    const float* Wk    = (const float*)d_in[3];
    const float* Wv    = (const float*)d_in[4];
    const float* Wrel  = (const float*)d_in[5];
    const float* pds   = (const float*)d_in[6];
    const float* Wpost = (const float*)d_in[7];
    float* out = (float*)d_out;

    const int attn_smem =
        ((CHUNK + CTX + CTX + PL) * ALD + CHUNK * CTX) * (int)sizeof(float);
    cudaFuncSetAttribute(attn_kernel,
                         cudaFuncAttributeMaxDynamicSharedMemorySize, attn_smem);

    prep_qscale<<<1, 192>>>(pds);
    relgemm<<<HID / 128, 128>>>(pe, Wrel);

    dim3 gq(HID / BN, (MTOT + BM - 1) / BM, 3);
    sgemm<0><<<gq, 256>>>(x, Wq, Wk, Wv, nullptr);

    dim3 ga(NB, NH, BATCH);
    attn_kernel<<<ga, 256, attn_smem>>>();

    dim3 gp(HID / BN, (MTOT + BM - 1) / BM, 1);
    sgemm<1><<<gp, 256>>>(nullptr, Wpost, nullptr, nullptr, out);
}

// round 5
// speedup vs baseline: 2.1709x; 2.1709x over previous
#include <cuda_runtime.h>
#include <cuda_bf16.h>
#include <math.h>
#include <stdint.h>

#define BATCH 4
#define SEQ 6007
#define HID 1536
#define NH 8
#define HD 192
#define CHUNK 12
#define MAX_PAST 12
#define CTX 24
#define PL 13
#define NB 501
#define SP (NB * CHUNK)          // 6012
#define MTOT (BATCH * SEQ)       // 24028
#define MPAD (BATCH * SP)        // 24048
#define MROUND 24064             // 188 * 128
#define SOFTCAP 50.0f

// ---------------- device scratch ----------------
__device__ float g_q[(size_t)MPAD * HID];
__device__ float g_k[(size_t)MPAD * HID];
__device__ float g_v[(size_t)MPAD * HID];
__device__ float g_rel[PL * HID];
__device__ float g_qscale[HD];

__device__ __nv_bfloat16 g_xhi[(size_t)MROUND * HID];
__device__ __nv_bfloat16 g_xlo[(size_t)MROUND * HID];
__device__ __nv_bfloat16 g_atthi[(size_t)MROUND * HID];
__device__ __nv_bfloat16 g_attlo[(size_t)MROUND * HID];
__device__ __nv_bfloat16 g_wthi[(size_t)4 * HID * HID];   // W^T [N,K], z-major
__device__ __nv_bfloat16 g_wtlo[(size_t)4 * HID * HID];

// ---------------- PTX helpers (sm_80+ baseline instructions only) ----------
__device__ __forceinline__ uint32_t smem_to_u32(const void* p) {
    uint32_t a;
    asm("{ .reg .u64 t; cvta.to.shared.u64 t, %1; cvt.u32.u64 %0, t; }" : "=r"(a) : "l"(p));
    return a;
}
__device__ __forceinline__ void cp16(uint32_t dst, const void* src) {
    asm volatile("cp.async.cg.shared.global [%0], [%1], 16;" :: "r"(dst), "l"(src));
}
__device__ __forceinline__ void cp_commit() { asm volatile("cp.async.commit_group;" ::: "memory"); }

__device__ __forceinline__ void ldsm4(uint32_t* r, uint32_t addr) {
    asm volatile("ldmatrix.sync.aligned.m8n8.x4.shared.b16 {%0,%1,%2,%3}, [%4];"
                 : "=r"(r[0]), "=r"(r[1]), "=r"(r[2]), "=r"(r[3]) : "r"(addr));
}
__device__ __forceinline__ void mma16816(float* d, const uint32_t* a, uint32_t b0, uint32_t b1) {
    asm volatile(
        "mma.sync.aligned.m16n8k16.row.col.f32.bf16.bf16.f32 "
        "{%0,%1,%2,%3}, {%4,%5,%6,%7}, {%8,%9}, {%0,%1,%2,%3};"
        : "+f"(d[0]), "+f"(d[1]), "+f"(d[2]), "+f"(d[3])
        : "r"(a[0]), "r"(a[1]), "r"(a[2]), "r"(a[3]), "r"(b0), "r"(b1));
}

#define SWZ128(o) ((o) ^ (((o) >> 3) & 0x70))

// ---------------- small prep kernels ----------------
__global__ void prep_qscale(const float* __restrict__ pds) {
    int d = threadIdx.x;
    if (d < HD) {
        float x = pds[d];
        float sp = (x > 20.f) ? x : log1pf(expf(x));
        const float qsc = (1.0f / sqrtf((float)HD)) * 1.4426950408889634f;
        g_qscale[d] = qsc * sp;
    }
}

__global__ void relgemm(const float* __restrict__ P, const float* __restrict__ W) {
    int n = blockIdx.x * 128 + threadIdx.x;
    float acc[PL];
#pragma unroll
    for (int p = 0; p < PL; p++) acc[p] = 0.f;
    for (int k = 0; k < HID; k++) {
        float w = W[(size_t)k * HID + n];
#pragma unroll
        for (int p = 0; p < PL; p++) acc[p] = fmaf(P[p * HID + k], w, acc[p]);
    }
#pragma unroll
    for (int p = 0; p < PL; p++) g_rel[p * HID + n] = acc[p];
}

__device__ __forceinline__ void split1(float v, __nv_bfloat16& hi, __nv_bfloat16& lo) {
    hi = __float2bfloat16(v);
    lo = __float2bfloat16(v - __bfloat162float(hi));
}

__global__ void xsplit(const float4* __restrict__ X) {
    size_t i = (size_t)blockIdx.x * blockDim.x + threadIdx.x;
    const size_t lim = (size_t)MTOT * HID / 4;
    float4 v = (i < lim) ? X[i] : make_float4(0.f, 0.f, 0.f, 0.f);
    __nv_bfloat162* H = (__nv_bfloat162*)g_xhi;
    __nv_bfloat162* L = (__nv_bfloat162*)g_xlo;
    __nv_bfloat162 h, l;
    split1(v.x, h.x, l.x); split1(v.y, h.y, l.y);
    H[2 * i] = h; L[2 * i] = l;
    split1(v.z, h.x, l.x); split1(v.w, h.y, l.y);
    H[2 * i + 1] = h; L[2 * i + 1] = l;
}

__global__ void wsplit(const float* __restrict__ W0, const float* __restrict__ W1,
                       const float* __restrict__ W2, const float* __restrict__ W3) {
    __shared__ float t[32][33];
    const int z = blockIdx.z;
    const float* W = (z == 0) ? W0 : (z == 1) ? W1 : (z == 2) ? W2 : W3;
    const int k0 = blockIdx.y * 32, n0 = blockIdx.x * 32;
    const int tx = threadIdx.x, ty = threadIdx.y;   // 32 x 8
#pragma unroll
    for (int r = 0; r < 32; r += 8)
        t[ty + r][tx] = W[(size_t)(k0 + ty + r) * HID + n0 + tx];
    __syncthreads();
    __nv_bfloat16* Oh = g_wthi + (size_t)z * HID * HID;
    __nv_bfloat16* Ol = g_wtlo + (size_t)z * HID * HID;
#pragma unroll
    for (int r = 0; r < 32; r += 8) {
        float v = t[tx][ty + r];
        __nv_bfloat16 hi, lo;
        split1(v, hi, lo);
        size_t o = (size_t)(n0 + ty + r) * HID + k0 + tx;
        Oh[o] = hi;
        Ol[o] = lo;
    }
}

// ---------------- bf16x3 mma.sync GEMM ----------------
// CTA tile 128(M) x 128(N), K-chunk 64. 8 warps: 2(M) x 4(N), warp tile 64x32.
// Per stage: AH, AL, BH, BL tiles of 128 rows x 128 bytes = 16 KB each.
#define BMT 128
#define BNT 128
#define BKC 64
#define NCHUNKS (HID / BKC)          // 24
#define OPTILE 16384                 // one operand tile
#define STAGE (4 * OPTILE)           // 65536
#define NSTAGE 3
#define GSMEM (NSTAGE * STAGE)       // 196608

// MODE 0: C = X @ W[z] -> g_q/g_k/g_v (padded rows, fp32), z==0 scaled by qscale
// MODE 1: Out = Att @ W[3] -> Out (contiguous fp32)
template <int MODE>
__global__ void __launch_bounds__(256, 1) tc_gemm(float* __restrict__ Out) {
    extern __shared__ char smem[];
    const uint32_t sbase = smem_to_u32(smem);
    const int tid = threadIdx.x;
    const int wid = tid >> 5;
    const int lane = tid & 31;
    const int z = blockIdx.z;
    const int n0 = blockIdx.x * BNT;
    const int m0 = blockIdx.y * BMT;

    const __nv_bfloat16* Ahi = (MODE == 0) ? g_xhi : g_atthi;
    const __nv_bfloat16* Alo = (MODE == 0) ? g_xlo : g_attlo;
    const size_t woff = (size_t)((MODE == 0) ? z : 3) * HID * HID;
    const __nv_bfloat16* Bhi = g_wthi + woff;
    const __nv_bfloat16* Blo = g_wtlo + woff;

    auto load_stage = [&](int st, int k0) {
        const uint32_t sb = sbase + st * STAGE;
#pragma unroll
        for (int it = 0; it < 4; it++) {
            int c = tid + it * 256;              // 0..1023
            int row = c >> 3, col = c & 7;
            uint32_t so = SWZ128((uint32_t)(row * 128 + col * 16));
            const char* ah = (const char*)(Ahi + (size_t)(m0 + row) * HID + k0) + col * 16;
            const char* al = (const char*)(Alo + (size_t)(m0 + row) * HID + k0) + col * 16;
            const char* bh = (const char*)(Bhi + (size_t)(n0 + row) * HID + k0) + col * 16;
            const char* bl = (const char*)(Blo + (size_t)(n0 + row) * HID + k0) + col * 16;
            cp16(sb + so, ah);
            cp16(sb + OPTILE + so, al);
            cp16(sb + 2 * OPTILE + so, bh);
            cp16(sb + 3 * OPTILE + so, bl);
        }
        cp_commit();
    };

    const int wm = (wid & 1) * 64;       // warp M offset in tile
    const int wn = (wid >> 1) * 32;      // warp N offset in tile

    float acc[4][4][4];
#pragma unroll
    for (int i = 0; i < 4; i++)
#pragma unroll
        for (int j = 0; j < 4; j++)
#pragma unroll
            for (int r = 0; r < 4; r++) acc[i][j][r] = 0.f;

    load_stage(0, 0);
    load_stage(1, BKC);

    const int arow_base = (lane & 15);
    const int kgrp = (lane >> 4) * 16;   // byte offset of k-half

    for (int i = 0; i < NCHUNKS; i++) {
        if (i < NCHUNKS - 1) {
            asm volatile("cp.async.wait_group 1;" ::: "memory");
        } else {
            asm volatile("cp.async.wait_group 0;" ::: "memory");
        }
        __syncthreads();
        if (i + 2 < NCHUNKS) load_stage((i + 2) % NSTAGE, (i + 2) * BKC);

        const uint32_t sb = sbase + (i % NSTAGE) * STAGE;
#pragma unroll
        for (int kk = 0; kk < 4; kk++) {
            const int kbyte = kk * 32 + kgrp;
            uint32_t ah[4][4], al[4][4];
#pragma unroll
            for (int mi = 0; mi < 4; mi++) {
                int row = wm + mi * 16 + arow_base;
                uint32_t off = SWZ128((uint32_t)(row * 128 + kbyte));
                ldsm4(ah[mi], sb + off);
                ldsm4(al[mi], sb + OPTILE + off);
            }
            uint32_t bh[2][4], bl[2][4];
#pragma unroll
            for (int ng = 0; ng < 2; ng++) {
                int row = wn + ng * 16 + arow_base;
                uint32_t off = SWZ128((uint32_t)(row * 128 + kbyte));
                ldsm4(bh[ng], sb + 2 * OPTILE + off);
                ldsm4(bl[ng], sb + 3 * OPTILE + off);
            }
#pragma unroll
            for (int mi = 0; mi < 4; mi++) {
#pragma unroll
                for (int nj = 0; nj < 4; nj++) {
                    const int ng = nj >> 1, sub = nj & 1;
                    mma16816(acc[mi][nj], ah[mi], bh[ng][sub], bh[ng][sub + 2]);
                    mma16816(acc[mi][nj], ah[mi], bl[ng][sub], bl[ng][sub + 2]);
                    mma16816(acc[mi][nj], al[mi], bh[ng][sub], bh[ng][sub + 2]);
                }
            }
        }
        __syncthreads();
    }

    // ---------------- epilogue ----------------
    const int frow = lane >> 2;          // 0..7
    const int fcol = (lane & 3) * 2;     // 0,2,4,6
#pragma unroll
    for (int mi = 0; mi < 4; mi++) {
#pragma unroll
        for (int half = 0; half < 2; half++) {
            int m = m0 + wm + mi * 16 + frow + half * 8;
            if (m >= MTOT) continue;
            float* orow;
            if (MODE == 0) {
                float* O = (z == 0) ? g_q : (z == 1) ? g_k : g_v;
                int bb = m / SEQ;
                int pr = bb * SP + (m - bb * SEQ);
                orow = O + (size_t)pr * HID;
            } else {
                orow = Out + (size_t)m * HID;
            }
#pragma unroll
            for (int nj = 0; nj < 4; nj++) {
                int col = n0 + wn + nj * 8 + fcol;
                float2 v;
                v.x = acc[mi][nj][half * 2 + 0];
                v.y = acc[mi][nj][half * 2 + 1];
                if (MODE == 0 && z == 0) {
                    v.x *= g_qscale[col % HD];
                    v.y *= g_qscale[(col + 1) % HD];
                }
                *(float2*)(orow + col) = v;
            }
        }
    }
}

// ---------------- blocked local attention ----------------
#define ALD 193

__global__ void attn_kernel() {
    extern __shared__ float sm[];
    float* qs = sm;
    float* ks = qs + CHUNK * ALD;
    float* vs = ks + CTX * ALD;
    float* rs = vs + CTX * ALD;
    float* sc = rs + PL * ALD;

    const int n = blockIdx.x;
    const int h = blockIdx.y;
    const int b = blockIdx.z;
    const int tid = threadIdx.x;

    const int base = b * SP + n * CHUNK;
    const size_t hoff = (size_t)h * HD;

    for (int e = tid; e < CHUNK * HD; e += 256) {
        int r = e / HD, d = e - r * HD;
        qs[r * ALD + d] = g_q[(size_t)(base + r) * HID + hoff + d];
    }
    for (int e = tid; e < CTX * HD; e += 256) {
        int r = e / HD, d = e - r * HD;
        int srow = base - MAX_PAST + r;
        float kk = 0.f, vv = 0.f;
        if (srow >= b * SP) {
            size_t off = (size_t)srow * HID + hoff + d;
            kk = g_k[off];
            vv = g_v[off];
        }
        ks[r * ALD + d] = kk;
        vs[r * ALD + d] = vv;
    }
    for (int e = tid; e < PL * HD; e += 256) {
        int p = e / HD, d = e - p * HD;
        rs[p * ALD + d] = g_rel[p * HID + hoff + d];
    }
    __syncthreads();

    for (int e = tid; e < CHUNK * CTX; e += 256) {
        int qi = e / CTX, c = e - qi * CTX;
        int absq = n * CHUNK + qi;
        int absk = n * CHUNK - MAX_PAST + c;
        bool valid = (absq < SEQ) && (absk >= 0) && (absk < SEQ) &&
                     (c > qi) && (c <= qi + MAX_PAST);
        float val = -1e9f;
        if (valid) {
            const float* qr = qs + qi * ALD;
            const float* kr = ks + c * ALD;
            const float* rr = rs + (c - qi) * ALD;
            float ac = 0.f, bd = 0.f;
#pragma unroll 8
            for (int d = 0; d < HD; d++) {
                float qv = qr[d];
                ac = fmaf(qv, kr[d], ac);
                bd = fmaf(qv, rr[d], bd);
            }
            float w = ac + bd;
            val = tanhf(w * (1.0f / SOFTCAP)) * SOFTCAP;
        }
        sc[e] = val;
    }
    __syncthreads();

    if (tid < CHUNK) {
        float* row = sc + tid * CTX;
        float mx = -1e30f;
#pragma unroll
        for (int c = 0; c < CTX; c++) mx = fmaxf(mx, row[c]);
        float s = 0.f;
#pragma unroll
        for (int c = 0; c < CTX; c++) {
            float e2 = __expf(row[c] - mx);
            row[c] = e2;
            s += e2;
        }
        float inv = 1.f / s;
#pragma unroll
        for (int c = 0; c < CTX; c++) row[c] *= inv;
    }
    __syncthreads();

    for (int e = tid; e < CHUNK * HD; e += 256) {
        int qi = e / HD, d = e - qi * HD;
        int absq = n * CHUNK + qi;
        if (absq >= SEQ) continue;
        const float* pr = sc + qi * CTX;
        float acc = 0.f;
#pragma unroll
        for (int c = 0; c < CTX; c++) acc = fmaf(pr[c], vs[c * ALD + d], acc);
        size_t o = (size_t)(b * SEQ + absq) * HID + hoff + d;
        __nv_bfloat16 hi, lo;
        split1(acc, hi, lo);
        g_atthi[o] = hi;
        g_attlo[o] = lo;
    }
}

// ---------------- launch ----------------
extern "C" void kernel_launch(void* const* d_in, const int* in_sizes, int n_in,
                              void* d_out, int out_size) {
    const float* x     = (const float*)d_in[0];
    const float* pe    = (const float*)d_in[1];
    const float* Wq    = (const float*)d_in[2];
    const float* Wk    = (const float*)d_in[3];
    const float* Wv    = (const float*)d_in[4];
    const float* Wrel  = (const float*)d_in[5];
    const float* pds   = (const float*)d_in[6];
    const float* Wpost = (const float*)d_in[7];
    float* out = (float*)d_out;

    const int attn_smem =
        ((CHUNK + CTX + CTX + PL) * ALD + CHUNK * CTX) * (int)sizeof(float);
    cudaFuncSetAttribute(attn_kernel,
                         cudaFuncAttributeMaxDynamicSharedMemorySize, attn_smem);
    cudaFuncSetAttribute(tc_gemm<0>,
                         cudaFuncAttributeMaxDynamicSharedMemorySize, GSMEM);
    cudaFuncSetAttribute(tc_gemm<1>,
                         cudaFuncAttributeMaxDynamicSharedMemorySize, GSMEM);

    prep_qscale<<<1, 192>>>(pds);
    relgemm<<<HID / 128, 128>>>(pe, Wrel);
    wsplit<<<dim3(48, 48, 4), dim3(32, 8)>>>(Wq, Wk, Wv, Wpost);
    xsplit<<<(int)((size_t)MROUND * HID / 4 / 256), 256>>>((const float4*)x);

    tc_gemm<0><<<dim3(HID / BNT, MROUND / BMT, 3), 256, GSMEM>>>(nullptr);

    attn_kernel<<<dim3(NB, NH, BATCH), 256, attn_smem>>>();

    tc_gemm<1><<<dim3(HID / BNT, MROUND / BMT, 1), 256, GSMEM>>>(out);
}

// round 6
// speedup vs baseline: 2.2225x; 1.0238x over previous
#include <cuda_runtime.h>
#include <cuda_bf16.h>
#include <math.h>
#include <stdint.h>

#define BATCH 4
#define SEQ 6007
#define HID 1536
#define NH 8
#define HD 192
#define CHUNK 12
#define MAX_PAST 12
#define CTX 24
#define PL 13
#define NB 501
#define SP (NB * CHUNK)          // 6012
#define MTOT (BATCH * SEQ)       // 24028
#define MPAD (BATCH * SP)        // 24048
#define MROUND 24064             // 94 * 256
#define SOFTCAP 50.0f

// ---------------- device scratch ----------------
__device__ float g_q[(size_t)MPAD * HID];
__device__ float g_k[(size_t)MPAD * HID];
__device__ float g_v[(size_t)MPAD * HID];
__device__ float g_rel[PL * HID];
__device__ float g_qscale[HD];

__device__ __nv_bfloat16 g_xhi[(size_t)MROUND * HID];
__device__ __nv_bfloat16 g_xlo[(size_t)MROUND * HID];
__device__ __nv_bfloat16 g_atthi[(size_t)MROUND * HID];
__device__ __nv_bfloat16 g_attlo[(size_t)MROUND * HID];
__device__ __nv_bfloat16 g_wthi[(size_t)4 * HID * HID];   // W^T [N,K], z-major
__device__ __nv_bfloat16 g_wtlo[(size_t)4 * HID * HID];

// ---------------- PTX helpers (sm_80+ baseline instructions only) ----------
__device__ __forceinline__ uint32_t smem_to_u32(const void* p) {
    uint32_t a;
    asm("{ .reg .u64 t; cvta.to.shared.u64 t, %1; cvt.u32.u64 %0, t; }" : "=r"(a) : "l"(p));
    return a;
}
__device__ __forceinline__ void cp16(uint32_t dst, const void* src) {
    asm volatile("cp.async.cg.shared.global [%0], [%1], 16;" :: "r"(dst), "l"(src));
}
__device__ __forceinline__ void cp_commit() { asm volatile("cp.async.commit_group;" ::: "memory"); }

__device__ __forceinline__ void ldsm4(uint32_t* r, uint32_t addr) {
    asm volatile("ldmatrix.sync.aligned.m8n8.x4.shared.b16 {%0,%1,%2,%3}, [%4];"
                 : "=r"(r[0]), "=r"(r[1]), "=r"(r[2]), "=r"(r[3]) : "r"(addr));
}
__device__ __forceinline__ void mma16816(float* d, const uint32_t* a, uint32_t b0, uint32_t b1) {
    asm volatile(
        "mma.sync.aligned.m16n8k16.row.col.f32.bf16.bf16.f32 "
        "{%0,%1,%2,%3}, {%4,%5,%6,%7}, {%8,%9}, {%0,%1,%2,%3};"
        : "+f"(d[0]), "+f"(d[1]), "+f"(d[2]), "+f"(d[3])
        : "r"(a[0]), "r"(a[1]), "r"(a[2]), "r"(a[3]), "r"(b0), "r"(b1));
}

#define SWZ128(o) ((o) ^ (((o) >> 3) & 0x70))

// ---------------- small prep kernels ----------------
__global__ void prep_qscale(const float* __restrict__ pds) {
    int d = threadIdx.x;
    if (d < HD) {
        float x = pds[d];
        float sp = (x > 20.f) ? x : log1pf(expf(x));
        const float qsc = (1.0f / sqrtf((float)HD)) * 1.4426950408889634f;
        g_qscale[d] = qsc * sp;
    }
}

__global__ void relgemm(const float* __restrict__ P, const float* __restrict__ W) {
    int n = blockIdx.x * 128 + threadIdx.x;
    float acc[PL];
#pragma unroll
    for (int p = 0; p < PL; p++) acc[p] = 0.f;
    for (int k = 0; k < HID; k++) {
        float w = W[(size_t)k * HID + n];
#pragma unroll
        for (int p = 0; p < PL; p++) acc[p] = fmaf(P[p * HID + k], w, acc[p]);
    }
#pragma unroll
    for (int p = 0; p < PL; p++) g_rel[p * HID + n] = acc[p];
}

__device__ __forceinline__ void split1(float v, __nv_bfloat16& hi, __nv_bfloat16& lo) {
    hi = __float2bfloat16(v);
    lo = __float2bfloat16(v - __bfloat162float(hi));
}

__global__ void xsplit(const float4* __restrict__ X) {
    size_t i = (size_t)blockIdx.x * blockDim.x + threadIdx.x;
    const size_t lim = (size_t)MTOT * HID / 4;
    float4 v = (i < lim) ? X[i] : make_float4(0.f, 0.f, 0.f, 0.f);
    __nv_bfloat162* H = (__nv_bfloat162*)g_xhi;
    __nv_bfloat162* L = (__nv_bfloat162*)g_xlo;
    __nv_bfloat162 h, l;
    split1(v.x, h.x, l.x); split1(v.y, h.y, l.y);
    H[2 * i] = h; L[2 * i] = l;
    split1(v.z, h.x, l.x); split1(v.w, h.y, l.y);
    H[2 * i + 1] = h; L[2 * i + 1] = l;
}

__global__ void wsplit(const float* __restrict__ W0, const float* __restrict__ W1,
                       const float* __restrict__ W2, const float* __restrict__ W3) {
    __shared__ float t[32][33];
    const int z = blockIdx.z;
    const float* W = (z == 0) ? W0 : (z == 1) ? W1 : (z == 2) ? W2 : W3;
    const int k0 = blockIdx.y * 32, n0 = blockIdx.x * 32;
    const int tx = threadIdx.x, ty = threadIdx.y;   // 32 x 8
#pragma unroll
    for (int r = 0; r < 32; r += 8)
        t[ty + r][tx] = W[(size_t)(k0 + ty + r) * HID + n0 + tx];
    __syncthreads();
    __nv_bfloat16* Oh = g_wthi + (size_t)z * HID * HID;
    __nv_bfloat16* Ol = g_wtlo + (size_t)z * HID * HID;
#pragma unroll
    for (int r = 0; r < 32; r += 8) {
        float v = t[tx][ty + r];
        __nv_bfloat16 hi, lo;
        split1(v, hi, lo);
        size_t o = (size_t)(n0 + ty + r) * HID + k0 + tx;
        Oh[o] = hi;
        Ol[o] = lo;
    }
}

// ---------------- bf16x3 mma.sync GEMM ----------------
// CTA tile 256(M) x 128(N), K-chunk 64. 512 threads, 16 warps: 4(M) x 4(N),
// warp tile 64x32. Per stage: AH/AL 32 KB each + BH/BL 16 KB each = 96 KB.
// 2 stages (192 KB), prefetch depth 1.
#define BMT 256
#define BNT 128
#define BKC 64
#define NCHUNKS (HID / BKC)          // 24
#define ATILE 32768                  // 256 rows * 128 B
#define BTILE 16384                  // 128 rows * 128 B
#define STAGE (2 * ATILE + 2 * BTILE)    // 98304
#define NSTAGE 2
#define GSMEM (NSTAGE * STAGE)           // 196608
#define GTHREADS 512

// MODE 0: C = X @ W[z] -> g_q/g_k/g_v (padded rows, fp32), z==0 scaled by qscale
// MODE 1: Out = Att @ W[3] -> Out (contiguous fp32)
template <int MODE>
__global__ void __launch_bounds__(GTHREADS, 1) tc_gemm(float* __restrict__ Out) {
    extern __shared__ char smem[];
    const uint32_t sbase = smem_to_u32(smem);
    const int tid = threadIdx.x;
    const int wid = tid >> 5;
    const int lane = tid & 31;
    const int z = blockIdx.z;
    const int n0 = blockIdx.x * BNT;
    const int m0 = blockIdx.y * BMT;

    const __nv_bfloat16* Ahi = (MODE == 0) ? g_xhi : g_atthi;
    const __nv_bfloat16* Alo = (MODE == 0) ? g_xlo : g_attlo;
    const size_t woff = (size_t)((MODE == 0) ? z : 3) * HID * HID;
    const __nv_bfloat16* Bhi = g_wthi + woff;
    const __nv_bfloat16* Blo = g_wtlo + woff;

    // 12 cp16 per thread per stage: 8 for A (hi+lo), 4 for B (hi+lo)
    auto load_stage = [&](int st, int k0) {
        const uint32_t sb = sbase + st * STAGE;
#pragma unroll
        for (int it = 0; it < 4; it++) {
            int c = tid + it * GTHREADS;         // 0..2047 -> 256 rows x 8 cols
            int row = c >> 3, col = c & 7;
            uint32_t so = SWZ128((uint32_t)(row * 128 + col * 16));
            const char* ah = (const char*)(Ahi + (size_t)(m0 + row) * HID + k0) + col * 16;
            const char* al = (const char*)(Alo + (size_t)(m0 + row) * HID + k0) + col * 16;
            cp16(sb + so, ah);
            cp16(sb + ATILE + so, al);
        }
#pragma unroll
        for (int it = 0; it < 2; it++) {
            int c = tid + it * GTHREADS;         // 0..1023 -> 128 rows x 8 cols
            int row = c >> 3, col = c & 7;
            uint32_t so = SWZ128((uint32_t)(row * 128 + col * 16));
            const char* bh = (const char*)(Bhi + (size_t)(n0 + row) * HID + k0) + col * 16;
            const char* bl = (const char*)(Blo + (size_t)(n0 + row) * HID + k0) + col * 16;
            cp16(sb + 2 * ATILE + so, bh);
            cp16(sb + 2 * ATILE + BTILE + so, bl);
        }
        cp_commit();
    };

    const int wm = (wid & 3) * 64;       // warp M offset in tile
    const int wn = (wid >> 2) * 32;      // warp N offset in tile

    float acc[4][4][4];
#pragma unroll
    for (int i = 0; i < 4; i++)
#pragma unroll
        for (int j = 0; j < 4; j++)
#pragma unroll
            for (int r = 0; r < 4; r++) acc[i][j][r] = 0.f;

    load_stage(0, 0);

    const int arow_base = (lane & 15);
    const int kgrp = (lane >> 4) * 16;   // byte offset of k-half

    for (int i = 0; i < NCHUNKS; i++) {
        // buffer (i+1)&1 held stage i-1, fully consumed + synced -> refill it
        if (i + 1 < NCHUNKS) {
            load_stage((i + 1) & 1, (i + 1) * BKC);
            asm volatile("cp.async.wait_group 1;" ::: "memory");   // stage i done
        } else {
            asm volatile("cp.async.wait_group 0;" ::: "memory");
        }
        __syncthreads();

        const uint32_t sb = sbase + (i & 1) * STAGE;
#pragma unroll
        for (int kk = 0; kk < 4; kk++) {
            const int kbyte = kk * 32 + kgrp;
            uint32_t ah[4][4], al[4][4];
#pragma unroll
            for (int mi = 0; mi < 4; mi++) {
                int row = wm + mi * 16 + arow_base;
                uint32_t off = SWZ128((uint32_t)(row * 128 + kbyte));
                ldsm4(ah[mi], sb + off);
                ldsm4(al[mi], sb + ATILE + off);
            }
            uint32_t bh[2][4], bl[2][4];
#pragma unroll
            for (int ng = 0; ng < 2; ng++) {
                int row = wn + ng * 16 + arow_base;
                uint32_t off = SWZ128((uint32_t)(row * 128 + kbyte));
                ldsm4(bh[ng], sb + 2 * ATILE + off);
                ldsm4(bl[ng], sb + 2 * ATILE + BTILE + off);
            }
#pragma unroll
            for (int mi = 0; mi < 4; mi++) {
#pragma unroll
                for (int nj = 0; nj < 4; nj++) {
                    const int ng = nj >> 1, sub = nj & 1;
                    mma16816(acc[mi][nj], ah[mi], bh[ng][sub], bh[ng][sub + 2]);
                    mma16816(acc[mi][nj], ah[mi], bl[ng][sub], bl[ng][sub + 2]);
                    mma16816(acc[mi][nj], al[mi], bh[ng][sub], bh[ng][sub + 2]);
                }
            }
        }
        __syncthreads();
    }

    // ---------------- epilogue ----------------
    const int frow = lane >> 2;          // 0..7
    const int fcol = (lane & 3) * 2;     // 0,2,4,6
#pragma unroll
    for (int mi = 0; mi < 4; mi++) {
#pragma unroll
        for (int half = 0; half < 2; half++) {
            int m = m0 + wm + mi * 16 + frow + half * 8;
            if (m >= MTOT) continue;
            float* orow;
            if (MODE == 0) {
                float* O = (z == 0) ? g_q : (z == 1) ? g_k : g_v;
                int bb = m / SEQ;
                int pr = bb * SP + (m - bb * SEQ);
                orow = O + (size_t)pr * HID;
            } else {
                orow = Out + (size_t)m * HID;
            }
#pragma unroll
            for (int nj = 0; nj < 4; nj++) {
                int col = n0 + wn + nj * 8 + fcol;
                float2 v;
                v.x = acc[mi][nj][half * 2 + 0];
                v.y = acc[mi][nj][half * 2 + 1];
                if (MODE == 0 && z == 0) {
                    v.x *= g_qscale[col % HD];
                    v.y *= g_qscale[(col + 1) % HD];
                }
                *(float2*)(orow + col) = v;
            }
        }
    }
}

// ---------------- blocked local attention ----------------
#define ALD 193

__global__ void attn_kernel() {
    extern __shared__ float sm[];
    float* qs = sm;
    float* ks = qs + CHUNK * ALD;
    float* vs = ks + CTX * ALD;
    float* rs = vs + CTX * ALD;
    float* sc = rs + PL * ALD;

    const int n = blockIdx.x;
    const int h = blockIdx.y;
    const int b = blockIdx.z;
    const int tid = threadIdx.x;

    const int base = b * SP + n * CHUNK;
    const size_t hoff = (size_t)h * HD;

    for (int e = tid; e < CHUNK * HD; e += 256) {
        int r = e / HD, d = e - r * HD;
        qs[r * ALD + d] = g_q[(size_t)(base + r) * HID + hoff + d];
    }
    for (int e = tid; e < CTX * HD; e += 256) {
        int r = e / HD, d = e - r * HD;
        int srow = base - MAX_PAST + r;
        float kk = 0.f, vv = 0.f;
        if (srow >= b * SP) {
            size_t off = (size_t)srow * HID + hoff + d;
            kk = g_k[off];
            vv = g_v[off];
        }
        ks[r * ALD + d] = kk;
        vs[r * ALD + d] = vv;
    }
    for (int e = tid; e < PL * HD; e += 256) {
        int p = e / HD, d = e - p * HD;
        rs[p * ALD + d] = g_rel[p * HID + hoff + d];
    }
    __syncthreads();

    for (int e = tid; e < CHUNK * CTX; e += 256) {
        int qi = e / CTX, c = e - qi * CTX;
        int absq = n * CHUNK + qi;
        int absk = n * CHUNK - MAX_PAST + c;
        bool valid = (absq < SEQ) && (absk >= 0) && (absk < SEQ) &&
                     (c > qi) && (c <= qi + MAX_PAST);
        float val = -1e9f;
        if (valid) {
            const float* qr = qs + qi * ALD;
            const float* kr = ks + c * ALD;
            const float* rr = rs + (c - qi) * ALD;
            float ac = 0.f, bd = 0.f;
#pragma unroll 8
            for (int d = 0; d < HD; d++) {
                float qv = qr[d];
                ac = fmaf(qv, kr[d], ac);
                bd = fmaf(qv, rr[d], bd);
            }
            float w = ac + bd;
            val = tanhf(w * (1.0f / SOFTCAP)) * SOFTCAP;
        }
        sc[e] = val;
    }
    __syncthreads();

    if (tid < CHUNK) {
        float* row = sc + tid * CTX;
        float mx = -1e30f;
#pragma unroll
        for (int c = 0; c < CTX; c++) mx = fmaxf(mx, row[c]);
        float s = 0.f;
#pragma unroll
        for (int c = 0; c < CTX; c++) {
            float e2 = __expf(row[c] - mx);
            row[c] = e2;
            s += e2;
        }
        float inv = 1.f / s;
#pragma unroll
        for (int c = 0; c < CTX; c++) row[c] *= inv;
    }
    __syncthreads();

    for (int e = tid; e < CHUNK * HD; e += 256) {
        int qi = e / HD, d = e - qi * HD;
        int absq = n * CHUNK + qi;
        if (absq >= SEQ) continue;
        const float* pr = sc + qi * CTX;
        float acc = 0.f;
#pragma unroll
        for (int c = 0; c < CTX; c++) acc = fmaf(pr[c], vs[c * ALD + d], acc);
        size_t o = (size_t)(b * SEQ + absq) * HID + hoff + d;
        __nv_bfloat16 hi, lo;
        split1(acc, hi, lo);
        g_atthi[o] = hi;
        g_attlo[o] = lo;
    }
}

// ---------------- launch ----------------
extern "C" void kernel_launch(void* const* d_in, const int* in_sizes, int n_in,
                              void* d_out, int out_size) {
    const float* x     = (const float*)d_in[0];
    const float* pe    = (const float*)d_in[1];
    const float* Wq    = (const float*)d_in[2];
    const float* Wk    = (const float*)d_in[3];
    const float* Wv    = (const float*)d_in[4];
    const float* Wrel  = (const float*)d_in[5];
    const float* pds   = (const float*)d_in[6];
    const float* Wpost = (const float*)d_in[7];
    float* out = (float*)d_out;

    const int attn_smem =
        ((CHUNK + CTX + CTX + PL) * ALD + CHUNK * CTX) * (int)sizeof(float);
    cudaFuncSetAttribute(attn_kernel,
                         cudaFuncAttributeMaxDynamicSharedMemorySize, attn_smem);
    cudaFuncSetAttribute(tc_gemm<0>,
                         cudaFuncAttributeMaxDynamicSharedMemorySize, GSMEM);
    cudaFuncSetAttribute(tc_gemm<1>,
                         cudaFuncAttributeMaxDynamicSharedMemorySize, GSMEM);

    prep_qscale<<<1, 192>>>(pds);
    relgemm<<<HID / 128, 128>>>(pe, Wrel);
    wsplit<<<dim3(48, 48, 4), dim3(32, 8)>>>(Wq, Wk, Wv, Wpost);
    xsplit<<<(int)((size_t)MROUND * HID / 4 / 256), 256>>>((const float4*)x);

    tc_gemm<0><<<dim3(HID / BNT, MROUND / BMT, 3), GTHREADS, GSMEM>>>(nullptr);

    attn_kernel<<<dim3(NB, NH, BATCH), 256, attn_smem>>>();

    tc_gemm<1><<<dim3(HID / BNT, MROUND / BMT, 1), GTHREADS, GSMEM>>>(out);
}

// round 8
// speedup vs baseline: 2.2488x; 1.0118x over previous
#include <cuda_runtime.h>
#include <cuda_bf16.h>
#include <math.h>
#include <stdint.h>

#define BATCH 4
#define SEQ 6007
#define HID 1536
#define NH 8
#define HD 192
#define CHUNK 12
#define MAX_PAST 12
#define CTX 24
#define PL 13
#define NB 501
#define SP (NB * CHUNK)          // 6012
#define MTOT (BATCH * SEQ)       // 24028
#define MPAD (BATCH * SP)        // 24048
#define MROUND 24064             // 94 * 256
#define SOFTCAP 50.0f

// ---------------- device scratch ----------------
__device__ float g_q[(size_t)MPAD * HID];
__device__ float g_k[(size_t)MPAD * HID];
__device__ float g_v[(size_t)MPAD * HID];
__device__ float g_rel[PL * HID];
__device__ float g_qscale[HD];

__device__ __nv_bfloat16 g_xhi[(size_t)MROUND * HID];
__device__ __nv_bfloat16 g_xlo[(size_t)MROUND * HID];
__device__ __nv_bfloat16 g_atthi[(size_t)MROUND * HID];
__device__ __nv_bfloat16 g_attlo[(size_t)MROUND * HID];
__device__ __nv_bfloat16 g_wthi[(size_t)4 * HID * HID];   // W^T [N,K], z-major
__device__ __nv_bfloat16 g_wtlo[(size_t)4 * HID * HID];

// ---------------- PTX helpers (sm_80+ baseline instructions only) ----------
__device__ __forceinline__ uint32_t smem_to_u32(const void* p) {
    uint32_t a;
    asm("{ .reg .u64 t; cvta.to.shared.u64 t, %1; cvt.u32.u64 %0, t; }" : "=r"(a) : "l"(p));
    return a;
}
__device__ __forceinline__ void cp16(uint32_t dst, const void* src) {
    asm volatile("cp.async.cg.shared.global [%0], [%1], 16;" :: "r"(dst), "l"(src));
}
__device__ __forceinline__ void cp_commit() { asm volatile("cp.async.commit_group;" ::: "memory"); }

__device__ __forceinline__ void ldsm4(uint32_t* r, uint32_t addr) {
    asm volatile("ldmatrix.sync.aligned.m8n8.x4.shared.b16 {%0,%1,%2,%3}, [%4];"
                 : "=r"(r[0]), "=r"(r[1]), "=r"(r[2]), "=r"(r[3]) : "r"(addr));
}
__device__ __forceinline__ void mma16816(float* d, const uint32_t* a, uint32_t b0, uint32_t b1) {
    asm volatile(
        "mma.sync.aligned.m16n8k16.row.col.f32.bf16.bf16.f32 "
        "{%0,%1,%2,%3}, {%4,%5,%6,%7}, {%8,%9}, {%0,%1,%2,%3};"
        : "+f"(d[0]), "+f"(d[1]), "+f"(d[2]), "+f"(d[3])
        : "r"(a[0]), "r"(a[1]), "r"(a[2]), "r"(a[3]), "r"(b0), "r"(b1));
}

#define SWZ128(o) ((o) ^ (((o) >> 3) & 0x70))

// ---------------- small prep kernels ----------------
__global__ void prep_qscale(const float* __restrict__ pds) {
    int d = threadIdx.x;
    if (d < HD) {
        float x = pds[d];
        float sp = (x > 20.f) ? x : log1pf(expf(x));
        const float qsc = (1.0f / sqrtf((float)HD)) * 1.4426950408889634f;
        g_qscale[d] = qsc * sp;
    }
}

__global__ void relgemm(const float* __restrict__ P, const float* __restrict__ W) {
    int n = blockIdx.x * 128 + threadIdx.x;
    float acc[PL];
#pragma unroll
    for (int p = 0; p < PL; p++) acc[p] = 0.f;
    for (int k = 0; k < HID; k++) {
        float w = W[(size_t)k * HID + n];
#pragma unroll
        for (int p = 0; p < PL; p++) acc[p] = fmaf(P[p * HID + k], w, acc[p]);
    }
#pragma unroll
    for (int p = 0; p < PL; p++) g_rel[p * HID + n] = acc[p];
}

__device__ __forceinline__ void split1(float v, __nv_bfloat16& hi, __nv_bfloat16& lo) {
    hi = __float2bfloat16(v);
    lo = __float2bfloat16(v - __bfloat162float(hi));
}

__global__ void xsplit(const float4* __restrict__ X) {
    size_t i = (size_t)blockIdx.x * blockDim.x + threadIdx.x;
    const size_t lim = (size_t)MTOT * HID / 4;
    float4 v = (i < lim) ? X[i] : make_float4(0.f, 0.f, 0.f, 0.f);
    __nv_bfloat162* H = (__nv_bfloat162*)g_xhi;
    __nv_bfloat162* L = (__nv_bfloat162*)g_xlo;
    __nv_bfloat162 h, l;
    split1(v.x, h.x, l.x); split1(v.y, h.y, l.y);
    H[2 * i] = h; L[2 * i] = l;
    split1(v.z, h.x, l.x); split1(v.w, h.y, l.y);
    H[2 * i + 1] = h; L[2 * i + 1] = l;
}

__global__ void wsplit(const float* __restrict__ W0, const float* __restrict__ W1,
                       const float* __restrict__ W2, const float* __restrict__ W3) {
    __shared__ float t[32][33];
    const int z = blockIdx.z;
    const float* W = (z == 0) ? W0 : (z == 1) ? W1 : (z == 2) ? W2 : W3;
    const int k0 = blockIdx.y * 32, n0 = blockIdx.x * 32;
    const int tx = threadIdx.x, ty = threadIdx.y;   // 32 x 8
#pragma unroll
    for (int r = 0; r < 32; r += 8)
        t[ty + r][tx] = W[(size_t)(k0 + ty + r) * HID + n0 + tx];
    __syncthreads();
    __nv_bfloat16* Oh = g_wthi + (size_t)z * HID * HID;
    __nv_bfloat16* Ol = g_wtlo + (size_t)z * HID * HID;
#pragma unroll
    for (int r = 0; r < 32; r += 8) {
        float v = t[tx][ty + r];
        __nv_bfloat16 hi, lo;
        split1(v, hi, lo);
        size_t o = (size_t)(n0 + ty + r) * HID + k0 + tx;
        Oh[o] = hi;
        Ol[o] = lo;
    }
}

// ---------------- bf16x3 mma.sync GEMM ----------------
// CTA tile 256(M) x 128(N), K-chunk 64. 256 threads, 8 warps: 4(M) x 2(N),
// warp tile 64x64 (cuts A-frag smem re-reads 4x -> 2x vs 64x32 warps).
// Per stage: AH/AL 32 KB each + BH/BL 16 KB each = 96 KB. 2 stages.
#define BMT 256
#define BNT 128
#define BKC 64
#define NCHUNKS (HID / BKC)          // 24
#define ATILE 32768                  // 256 rows * 128 B
#define BTILE 16384                  // 128 rows * 128 B
#define STAGE (2 * ATILE + 2 * BTILE)    // 98304
#define GSMEM (2 * STAGE)                // 196608
#define GTHREADS 256

// MODE 0: C = X @ W[z] -> g_q/g_k/g_v (padded rows, fp32), z==0 scaled by qscale
// MODE 1: Out = Att @ W[3] -> Out (contiguous fp32)
template <int MODE>
__global__ void __launch_bounds__(GTHREADS, 1) tc_gemm(float* __restrict__ Out) {
    extern __shared__ char smem[];
    const uint32_t sbase = smem_to_u32(smem);
    const int tid = threadIdx.x;
    const int wid = tid >> 5;
    const int lane = tid & 31;
    const int z = blockIdx.z;
    const int n0 = blockIdx.x * BNT;
    const int m0 = blockIdx.y * BMT;

    const __nv_bfloat16* Ahi = (MODE == 0) ? g_xhi : g_atthi;
    const __nv_bfloat16* Alo = (MODE == 0) ? g_xlo : g_attlo;
    const size_t woff = (size_t)((MODE == 0) ? z : 3) * HID * HID;
    const __nv_bfloat16* Bhi = g_wthi + woff;
    const __nv_bfloat16* Blo = g_wtlo + woff;

    // 24 cp16 per thread per stage: 16 for A (hi+lo), 8 for B (hi+lo)
    auto load_stage = [&](int st, int k0) {
        const uint32_t sb = sbase + st * STAGE;
#pragma unroll
        for (int it = 0; it < 8; it++) {
            int c = tid + it * GTHREADS;         // 0..2047 -> 256 rows x 8 cols
            int row = c >> 3, col = c & 7;
            uint32_t so = SWZ128((uint32_t)(row * 128 + col * 16));
            const char* ah = (const char*)(Ahi + (size_t)(m0 + row) * HID + k0) + col * 16;
            const char* al = (const char*)(Alo + (size_t)(m0 + row) * HID + k0) + col * 16;
            cp16(sb + so, ah);
            cp16(sb + ATILE + so, al);
        }
#pragma unroll
        for (int it = 0; it < 4; it++) {
            int c = tid + it * GTHREADS;         // 0..1023 -> 128 rows x 8 cols
            int row = c >> 3, col = c & 7;
            uint32_t so = SWZ128((uint32_t)(row * 128 + col * 16));
            const char* bh = (const char*)(Bhi + (size_t)(n0 + row) * HID + k0) + col * 16;
            const char* bl = (const char*)(Blo + (size_t)(n0 + row) * HID + k0) + col * 16;
            cp16(sb + 2 * ATILE + so, bh);
            cp16(sb + 2 * ATILE + BTILE + so, bl);
        }
        cp_commit();
    };

    const int wm = (wid & 3) * 64;       // warp M offset in tile
    const int wn = (wid >> 2) * 64;      // warp N offset in tile

    float acc[4][8][4];
#pragma unroll
    for (int i = 0; i < 4; i++)
#pragma unroll
        for (int j = 0; j < 8; j++)
#pragma unroll
            for (int r = 0; r < 4; r++) acc[i][j][r] = 0.f;

    load_stage(0, 0);

    const int arow_base = (lane & 15);
    const int kgrp = (lane >> 4) * 16;   // byte offset of k-half

    for (int i = 0; i < NCHUNKS; i++) {
        // buffer (i+1)&1 held stage i-1, fully consumed + synced -> refill it
        if (i + 1 < NCHUNKS) {
            load_stage((i + 1) & 1, (i + 1) * BKC);
            asm volatile("cp.async.wait_group 1;" ::: "memory");   // stage i done
        } else {
            asm volatile("cp.async.wait_group 0;" ::: "memory");
        }
        __syncthreads();

        const uint32_t sb = sbase + (i & 1) * STAGE;
#pragma unroll
        for (int kk = 0; kk < 4; kk++) {
            const int kbyte = kk * 32 + kgrp;
            uint32_t ah[4][4], al[4][4];
#pragma unroll
            for (int mi = 0; mi < 4; mi++) {
                int row = wm + mi * 16 + arow_base;
                uint32_t off = SWZ128((uint32_t)(row * 128 + kbyte));
                ldsm4(ah[mi], sb + off);
                ldsm4(al[mi], sb + ATILE + off);
            }
            uint32_t bh[4][4], bl[4][4];
#pragma unroll
            for (int ng = 0; ng < 4; ng++) {
                int row = wn + ng * 16 + arow_base;
                uint32_t off = SWZ128((uint32_t)(row * 128 + kbyte));
                ldsm4(bh[ng], sb + 2 * ATILE + off);
                ldsm4(bl[ng], sb + 2 * ATILE + BTILE + off);
            }
#pragma unroll
            for (int mi = 0; mi < 4; mi++) {
#pragma unroll
                for (int nj = 0; nj < 8; nj++) {
                    const int ng = nj >> 1, sub = nj & 1;
                    mma16816(acc[mi][nj], ah[mi], bh[ng][sub], bh[ng][sub + 2]);
                    mma16816(acc[mi][nj], ah[mi], bl[ng][sub], bl[ng][sub + 2]);
                    mma16816(acc[mi][nj], al[mi], bh[ng][sub], bh[ng][sub + 2]);
                }
            }
        }
        __syncthreads();
    }

    // ---------------- epilogue ----------------
    const int frow = lane >> 2;          // 0..7
    const int fcol = (lane & 3) * 2;     // 0,2,4,6
#pragma unroll
    for (int mi = 0; mi < 4; mi++) {
#pragma unroll
        for (int half = 0; half < 2; half++) {
            int m = m0 + wm + mi * 16 + frow + half * 8;
            if (m >= MTOT) continue;
            float* orow;
            if (MODE == 0) {
                float* O = (z == 0) ? g_q : (z == 1) ? g_k : g_v;
                int bb = m / SEQ;
                int pr = bb * SP + (m - bb * SEQ);
                orow = O + (size_t)pr * HID;
            } else {
                orow = Out + (size_t)m * HID;
            }
#pragma unroll
            for (int nj = 0; nj < 8; nj++) {
                int col = n0 + wn + nj * 8 + fcol;
                float2 v;
                v.x = acc[mi][nj][half * 2 + 0];
                v.y = acc[mi][nj][half * 2 + 1];
                if (MODE == 0 && z == 0) {
                    v.x *= g_qscale[col % HD];
                    v.y *= g_qscale[(col + 1) % HD];
                }
                *(float2*)(orow + col) = v;
            }
        }
    }
}

// ---------------- blocked local attention ----------------
#define ALD 193

__global__ void attn_kernel() {
    extern __shared__ float sm[];
    float* qs = sm;
    float* ks = qs + CHUNK * ALD;
    float* vs = ks + CTX * ALD;
    float* rs = vs + CTX * ALD;
    float* sc = rs + PL * ALD;

    const int n = blockIdx.x;
    const int h = blockIdx.y;
    const int b = blockIdx.z;
    const int tid = threadIdx.x;

    const int base = b * SP + n * CHUNK;
    const size_t hoff = (size_t)h * HD;

    for (int e = tid; e < CHUNK * HD; e += 256) {
        int r = e / HD, d = e - r * HD;
        qs[r * ALD + d] = g_q[(size_t)(base + r) * HID + hoff + d];
    }
    for (int e = tid; e < CTX * HD; e += 256) {
        int r = e / HD, d = e - r * HD;
        int srow = base - MAX_PAST + r;
        float kk = 0.f, vv = 0.f;
        if (srow >= b * SP) {
            size_t off = (size_t)srow * HID + hoff + d;
            kk = g_k[off];
            vv = g_v[off];
        }
        ks[r * ALD + d] = kk;
        vs[r * ALD + d] = vv;
    }
    for (int e = tid; e < PL * HD; e += 256) {
        int p = e / HD, d = e - p * HD;
        rs[p * ALD + d] = g_rel[p * HID + hoff + d];
    }
    __syncthreads();

    for (int e = tid; e < CHUNK * CTX; e += 256) {
        int qi = e / CTX, c = e - qi * CTX;
        int absq = n * CHUNK + qi;
        int absk = n * CHUNK - MAX_PAST + c;
        bool valid = (absq < SEQ) && (absk >= 0) && (absk < SEQ) &&
                     (c > qi) && (c <= qi + MAX_PAST);
        float val = -1e9f;
        if (valid) {
            const float* qr = qs + qi * ALD;
            const float* kr = ks + c * ALD;
            const float* rr = rs + (c - qi) * ALD;
            float ac = 0.f, bd = 0.f;
#pragma unroll 8
            for (int d = 0; d < HD; d++) {
                float qv = qr[d];
                ac = fmaf(qv, kr[d], ac);
                bd = fmaf(qv, rr[d], bd);
            }
            float w = ac + bd;
            val = tanhf(w * (1.0f / SOFTCAP)) * SOFTCAP;
        }
        sc[e] = val;
    }
    __syncthreads();

    if (tid < CHUNK) {
        float* row = sc + tid * CTX;
        float mx = -1e30f;
#pragma unroll
        for (int c = 0; c < CTX; c++) mx = fmaxf(mx, row[c]);
        float s = 0.f;
#pragma unroll
        for (int c = 0; c < CTX; c++) {
            float e2 = __expf(row[c] - mx);
            row[c] = e2;
            s += e2;
        }
        float inv = 1.f / s;
#pragma unroll
        for (int c = 0; c < CTX; c++) row[c] *= inv;
    }
    __syncthreads();

    for (int e = tid; e < CHUNK * HD; e += 256) {
        int qi = e / HD, d = e - qi * HD;
        int absq = n * CHUNK + qi;
        if (absq >= SEQ) continue;
        const float* pr = sc + qi * CTX;
        float acc = 0.f;
#pragma unroll
        for (int c = 0; c < CTX; c++) acc = fmaf(pr[c], vs[c * ALD + d], acc);
        size_t o = (size_t)(b * SEQ + absq) * HID + hoff + d;
        __nv_bfloat16 hi, lo;
        split1(acc, hi, lo);
        g_atthi[o] = hi;
        g_attlo[o] = lo;
    }
}

// ---------------- launch ----------------
extern "C" void kernel_launch(void* const* d_in, const int* in_sizes, int n_in,
                              void* d_out, int out_size) {
    const float* x     = (const float*)d_in[0];
    const float* pe    = (const float*)d_in[1];
    const float* Wq    = (const float*)d_in[2];
    const float* Wk    = (const float*)d_in[3];
    const float* Wv    = (const float*)d_in[4];
    const float* Wrel  = (const float*)d_in[5];
    const float* pds   = (const float*)d_in[6];
    const float* Wpost = (const float*)d_in[7];
    float* out = (float*)d_out;

    const int attn_smem =
        ((CHUNK + CTX + CTX + PL) * ALD + CHUNK * CTX) * (int)sizeof(float);
    cudaFuncSetAttribute(attn_kernel,
                         cudaFuncAttributeMaxDynamicSharedMemorySize, attn_smem);
    cudaFuncSetAttribute(tc_gemm<0>,
                         cudaFuncAttributeMaxDynamicSharedMemorySize, GSMEM);
    cudaFuncSetAttribute(tc_gemm<1>,
                         cudaFuncAttributeMaxDynamicSharedMemorySize, GSMEM);

    prep_qscale<<<1, 192>>>(pds);
    relgemm<<<HID / 128, 128>>>(pe, Wrel);
    wsplit<<<dim3(48, 48, 4), dim3(32, 8)>>>(Wq, Wk, Wv, Wpost);
    xsplit<<<(int)((size_t)MROUND * HID / 4 / 256), 256>>>((const float4*)x);

    tc_gemm<0><<<dim3(HID / BNT, MROUND / BMT, 3), GTHREADS, GSMEM>>>(nullptr);

    attn_kernel<<<dim3(NB, NH, BATCH), 256, attn_smem>>>();

    tc_gemm<1><<<dim3(HID / BNT, MROUND / BMT, 1), GTHREADS, GSMEM>>>(out);
}

// round 10
// speedup vs baseline: 3.1468x; 1.3993x over previous
#include <cuda_runtime.h>
#include <cuda_bf16.h>
#include <math.h>
#include <stdint.h>

#define BATCH 4
#define SEQ 6007
#define HID 1536
#define NH 8
#define HD 192
#define CHUNK 12
#define MAX_PAST 12
#define CTX 24
#define PL 13
#define NB 501
#define SP (NB * CHUNK)          // 6012
#define MTOT (BATCH * SEQ)       // 24028
#define MPAD (BATCH * SP)        // 24048
#define MROUND 24064             // 188 * 128
#define SOFTCAP 50.0f

// ---------------- device scratch ----------------
__device__ float g_q[(size_t)MPAD * HID];
__device__ float g_k[(size_t)MPAD * HID];
__device__ float g_v[(size_t)MPAD * HID];
__device__ float g_att[(size_t)MTOT * HID];
__device__ float g_rel[PL * HID];
__device__ float g_qscale[HD];

// int8 two-level quantized operands (pad rows stay zero-initialized)
__device__ int8_t g_xq1[(size_t)MROUND * HID];
__device__ int8_t g_xq2[(size_t)MROUND * HID];
__device__ int8_t g_aq1[(size_t)MROUND * HID];
__device__ int8_t g_aq2[(size_t)MROUND * HID];
__device__ int8_t g_wq1[(size_t)4 * HID * HID];   // W^T [N,K], z-major
__device__ int8_t g_wq2[(size_t)4 * HID * HID];
__device__ float g_sax[MROUND];                    // per-row scale of x
__device__ float g_saa[MROUND];                    // per-row scale of att
__device__ float g_sbw[4 * HID];                   // per-col scale of W[z]

// ---------------- PTX helpers (sm_80+ baseline instructions only) ----------
__device__ __forceinline__ uint32_t smem_to_u32(const void* p) {
    uint32_t a;
    asm("{ .reg .u64 t; cvta.to.shared.u64 t, %1; cvt.u32.u64 %0, t; }" : "=r"(a) : "l"(p));
    return a;
}
__device__ __forceinline__ void cp16(uint32_t dst, const void* src) {
    asm volatile("cp.async.cg.shared.global [%0], [%1], 16;" :: "r"(dst), "l"(src));
}
__device__ __forceinline__ void cp_commit() { asm volatile("cp.async.commit_group;" ::: "memory"); }

__device__ __forceinline__ void ldsm4(uint32_t* r, uint32_t addr) {
    asm volatile("ldmatrix.sync.aligned.m8n8.x4.shared.b16 {%0,%1,%2,%3}, [%4];"
                 : "=r"(r[0]), "=r"(r[1]), "=r"(r[2]), "=r"(r[3]) : "r"(addr));
}
// int8 IMMA: D(s32) += A(s8,16x32) * B(s8,32x8)
__device__ __forceinline__ void imma16832(int* d, const uint32_t* a, uint32_t b0, uint32_t b1) {
    asm volatile(
        "mma.sync.aligned.m16n8k32.row.col.s32.s8.s8.s32 "
        "{%0,%1,%2,%3}, {%4,%5,%6,%7}, {%8,%9}, {%0,%1,%2,%3};"
        : "+r"(d[0]), "+r"(d[1]), "+r"(d[2]), "+r"(d[3])
        : "r"(a[0]), "r"(a[1]), "r"(a[2]), "r"(a[3]), "r"(b0), "r"(b1));
}

#define SWZ128(o) ((o) ^ (((o) >> 3) & 0x70))

// ---------------- small prep kernels ----------------
__global__ void prep_qscale(const float* __restrict__ pds) {
    int d = threadIdx.x;
    if (d < HD) {
        float x = pds[d];
        float sp = (x > 20.f) ? x : log1pf(expf(x));
        const float qsc = (1.0f / sqrtf((float)HD)) * 1.4426950408889634f;
        g_qscale[d] = qsc * sp;
    }
}

__global__ void relgemm(const float* __restrict__ P, const float* __restrict__ W) {
    int n = blockIdx.x * 128 + threadIdx.x;
    float acc[PL];
#pragma unroll
    for (int p = 0; p < PL; p++) acc[p] = 0.f;
    for (int k = 0; k < HID; k++) {
        float w = W[(size_t)k * HID + n];
#pragma unroll
        for (int p = 0; p < PL; p++) acc[p] = fmaf(P[p * HID + k], w, acc[p]);
    }
#pragma unroll
    for (int p = 0; p < PL; p++) g_rel[p * HID + n] = acc[p];
}

__device__ __forceinline__ int8_t q8(float v) {
    int q = (int)rintf(v);
    q = (q > 127) ? 127 : ((q < -127) ? -127 : q);
    return (int8_t)q;
}

// two-level int8 row quantization: one warp per row of 1536 fp32.
// SRC 0: src = xsrc -> g_xq1/g_xq2/g_sax ; SRC 1: src = g_att -> g_aq1/g_aq2/g_saa
template <int SRC>
__global__ void quant_rows(const float4* __restrict__ xsrc) {
    const int warp = threadIdx.x >> 5;
    const int lane = threadIdx.x & 31;
    const int row = blockIdx.x * 8 + warp;
    if (row >= MTOT) return;

    const float4* src = (SRC == 0) ? (xsrc + (size_t)row * (HID / 4))
                                   : ((const float4*)g_att + (size_t)row * (HID / 4));
    float4 v[12];
    float amax = 0.f;
#pragma unroll
    for (int it = 0; it < 12; it++) {
        v[it] = src[lane + it * 32];
        amax = fmaxf(amax, fmaxf(fmaxf(fabsf(v[it].x), fabsf(v[it].y)),
                                 fmaxf(fabsf(v[it].z), fabsf(v[it].w))));
    }
#pragma unroll
    for (int s = 16; s > 0; s >>= 1)
        amax = fmaxf(amax, __shfl_xor_sync(0xFFFFFFFF, amax, s));

    const float sa = fmaxf(amax, 1e-30f) * (1.0f / 127.0f);
    const float inv1 = 1.0f / sa;
    const float inv2 = 254.0f / sa;
    const float sa2 = sa * (1.0f / 254.0f);

    int8_t* q1o = (SRC == 0) ? g_xq1 : g_aq1;
    int8_t* q2o = (SRC == 0) ? g_xq2 : g_aq2;
    if (lane == 0) ((SRC == 0) ? g_sax : g_saa)[row] = sa;

#pragma unroll
    for (int it = 0; it < 12; it++) {
        char4 c1, c2;
        float f[4] = {v[it].x, v[it].y, v[it].z, v[it].w};
        int8_t a1[4], a2[4];
#pragma unroll
        for (int j = 0; j < 4; j++) {
            int8_t qq = q8(f[j] * inv1);
            float r = f[j] - (float)qq * sa;
            a1[j] = qq;
            a2[j] = q8(r * (inv2 * 0.f + 1.f / sa2));   // r / sa2
        }
        c1.x = a1[0]; c1.y = a1[1]; c1.z = a1[2]; c1.w = a1[3];
        c2.x = a2[0]; c2.y = a2[1]; c2.z = a2[2]; c2.w = a2[3];
        size_t o = (size_t)row * HID + (lane + it * 32) * 4;
        *(char4*)(q1o + o) = c1;
        *(char4*)(q2o + o) = c2;
    }
}

// W quantize + transpose: block handles 32 N-cols of one W, full K.
// Phase 1: column max; Phase 2: 32x32 smem-tiled transpose + 2-level quantize.
__global__ void wquant(const float* __restrict__ W0, const float* __restrict__ W1,
                       const float* __restrict__ W2, const float* __restrict__ W3) {
    __shared__ float red[8][32];
    __shared__ float sbv[32];
    __shared__ float t[32][33];

    const int z = blockIdx.y;
    const float* W = (z == 0) ? W0 : (z == 1) ? W1 : (z == 2) ? W2 : W3;
    const int n0 = blockIdx.x * 32;
    const int tx = threadIdx.x, ty = threadIdx.y;   // 32 x 8

    float m = 0.f;
    for (int k = ty; k < HID; k += 8)
        m = fmaxf(m, fabsf(W[(size_t)k * HID + n0 + tx]));
    red[ty][tx] = m;
    __syncthreads();
    if (ty == 0) {
#pragma unroll
        for (int r = 1; r < 8; r++) m = fmaxf(m, red[r][tx]);
        float sb = fmaxf(m, 1e-30f) * (1.0f / 127.0f);
        sbv[tx] = sb;
        g_sbw[z * HID + n0 + tx] = sb;
    }
    __syncthreads();

    int8_t* Oq1 = g_wq1 + (size_t)z * HID * HID;
    int8_t* Oq2 = g_wq2 + (size_t)z * HID * HID;
    for (int k0 = 0; k0 < HID; k0 += 32) {
#pragma unroll
        for (int r = 0; r < 32; r += 8)
            t[ty + r][tx] = W[(size_t)(k0 + ty + r) * HID + n0 + tx];
        __syncthreads();
#pragma unroll
        for (int r = 0; r < 32; r += 8) {
            int n = ty + r;                  // local n index
            float sb = sbv[n];
            float v = t[tx][n];              // W[k0+tx][n0+n]
            int8_t qq = q8(v / sb);
            float res = v - (float)qq * sb;
            int8_t q2v = q8(res * (254.0f / sb));
            size_t o = (size_t)(n0 + n) * HID + k0 + tx;
            Oq1[o] = qq;
            Oq2[o] = q2v;
        }
        __syncthreads();
    }
}

// ---------------- int8x3 mma.sync GEMM ----------------
// CTA tile 128(M) x 128(N), K-chunk 128 (native 128B int8 rows, SW128).
// 256 threads, 8 warps: 2(M) x 4(N), warp tile 64x32.
// Per stage: AQ1/AQ2 16 KB each + BQ1/BQ2 16 KB each = 64 KB. 3 stages.
#define BMT 128
#define BNT 128
#define BKC 128
#define NCHUNKS (HID / BKC)          // 12
#define QTILE 16384                  // 128 rows * 128 B
#define STAGE (4 * QTILE)            // 65536
#define NSTAGE 3
#define GSMEM (NSTAGE * STAGE)       // 196608
#define GTHREADS 256

// MODE 0: C = X @ W[z] -> g_q/g_k/g_v (padded rows, fp32), z==0 scaled by qscale
// MODE 1: Out = Att @ W[3] -> Out (contiguous fp32)
template <int MODE>
__global__ void __launch_bounds__(GTHREADS, 1) tc_gemm(float* __restrict__ Out) {
    extern __shared__ char smem[];
    const uint32_t sbase = smem_to_u32(smem);
    const int tid = threadIdx.x;
    const int wid = tid >> 5;
    const int lane = tid & 31;
    const int z = blockIdx.z;
    const int n0 = blockIdx.x * BNT;
    const int m0 = blockIdx.y * BMT;

    const int8_t* Aq1 = (MODE == 0) ? g_xq1 : g_aq1;
    const int8_t* Aq2 = (MODE == 0) ? g_xq2 : g_aq2;
    const int zsel = (MODE == 0) ? z : 3;
    const int8_t* Bq1 = g_wq1 + (size_t)zsel * HID * HID;
    const int8_t* Bq2 = g_wq2 + (size_t)zsel * HID * HID;

    // 16 cp16 per thread per stage (4 each for AQ1/AQ2/BQ1/BQ2)
    auto load_stage = [&](int st, int k0) {
        const uint32_t sb = sbase + st * STAGE;
#pragma unroll
        for (int it = 0; it < 4; it++) {
            int c = tid + it * GTHREADS;         // 0..1023 -> 128 rows x 8 cols
            int row = c >> 3, col = c & 7;
            uint32_t so = SWZ128((uint32_t)(row * 128 + col * 16));
            const int8_t* a1 = Aq1 + (size_t)(m0 + row) * HID + k0 + col * 16;
            const int8_t* a2 = Aq2 + (size_t)(m0 + row) * HID + k0 + col * 16;
            const int8_t* b1 = Bq1 + (size_t)(n0 + row) * HID + k0 + col * 16;
            const int8_t* b2 = Bq2 + (size_t)(n0 + row) * HID + k0 + col * 16;
            cp16(sb + so, a1);
            cp16(sb + QTILE + so, a2);
            cp16(sb + 2 * QTILE + so, b1);
            cp16(sb + 3 * QTILE + so, b2);
        }
        cp_commit();
    };

    const int wm = (wid & 1) * 64;       // warp M offset
    const int wn = (wid >> 1) * 32;      // warp N offset

    int P1[4][4][4], P23[4][4][4];
#pragma unroll
    for (int i = 0; i < 4; i++)
#pragma unroll
        for (int j = 0; j < 4; j++)
#pragma unroll
            for (int r = 0; r < 4; r++) { P1[i][j][r] = 0; P23[i][j][r] = 0; }

    load_stage(0, 0);
    load_stage(1, BKC);

    const int arow_base = (lane & 15);
    const int kgrp = (lane >> 4) * 16;   // byte offset of k-half

    for (int i = 0; i < NCHUNKS; i++) {
        if (i < NCHUNKS - 1) {
            asm volatile("cp.async.wait_group 1;" ::: "memory");
        } else {
            asm volatile("cp.async.wait_group 0;" ::: "memory");
        }
        __syncthreads();
        if (i + 2 < NCHUNKS) load_stage((i + 2) % NSTAGE, (i + 2) * BKC);

        const uint32_t sb = sbase + (i % NSTAGE) * STAGE;
#pragma unroll
        for (int kk = 0; kk < 4; kk++) {         // k32 steps within k128 chunk
            const int kbyte = kk * 32 + kgrp;
            uint32_t a1[4][4], a2[4][4];
#pragma unroll
            for (int mi = 0; mi < 4; mi++) {
                int row = wm + mi * 16 + arow_base;
                uint32_t off = SWZ128((uint32_t)(row * 128 + kbyte));
                ldsm4(a1[mi], sb + off);
                ldsm4(a2[mi], sb + QTILE + off);
            }
            uint32_t b1[2][4], b2[2][4];
#pragma unroll
            for (int ng = 0; ng < 2; ng++) {
                int row = wn + ng * 16 + arow_base;
                uint32_t off = SWZ128((uint32_t)(row * 128 + kbyte));
                ldsm4(b1[ng], sb + 2 * QTILE + off);
                ldsm4(b2[ng], sb + 3 * QTILE + off);
            }
#pragma unroll
            for (int mi = 0; mi < 4; mi++) {
#pragma unroll
                for (int nj = 0; nj < 4; nj++) {
                    const int ng = nj >> 1, sub = nj & 1;
                    imma16832(P1[mi][nj],  a1[mi], b1[ng][sub], b1[ng][sub + 2]);
                    imma16832(P23[mi][nj], a1[mi], b2[ng][sub], b2[ng][sub + 2]);
                    imma16832(P23[mi][nj], a2[mi], b1[ng][sub], b1[ng][sub + 2]);
                }
            }
        }
        __syncthreads();
    }

    // ---------------- epilogue: C = sa*sb*(P1 + P23/254) ----------------
    const int frow = lane >> 2;          // 0..7
    const int fcol = (lane & 3) * 2;     // 0,2,4,6
    const float* sarr = (MODE == 0) ? g_sax : g_saa;
#pragma unroll
    for (int mi = 0; mi < 4; mi++) {
#pragma unroll
        for (int half = 0; half < 2; half++) {
            int m = m0 + wm + mi * 16 + frow + half * 8;
            if (m >= MTOT) continue;
            float sa = sarr[m];
            float* orow;
            if (MODE == 0) {
                float* O = (z == 0) ? g_q : (z == 1) ? g_k : g_v;
                int bb = m / SEQ;
                int pr = bb * SP + (m - bb * SEQ);
                orow = O + (size_t)pr * HID;
            } else {
                orow = Out + (size_t)m * HID;
            }
#pragma unroll
            for (int nj = 0; nj < 4; nj++) {
                int col = n0 + wn + nj * 8 + fcol;
                float sb0 = g_sbw[zsel * HID + col];
                float sb1 = g_sbw[zsel * HID + col + 1];
                float vx = sa * sb0 * ((float)P1[mi][nj][half * 2 + 0] +
                                       (float)P23[mi][nj][half * 2 + 0] * (1.0f / 254.0f));
                float vy = sa * sb1 * ((float)P1[mi][nj][half * 2 + 1] +
                                       (float)P23[mi][nj][half * 2 + 1] * (1.0f / 254.0f));
                if (MODE == 0 && z == 0) {
                    vx *= g_qscale[col % HD];
                    vy *= g_qscale[(col + 1) % HD];
                }
                float2 v2; v2.x = vx; v2.y = vy;
                *(float2*)(orow + col) = v2;
            }
        }
    }
}

// ---------------- blocked local attention ----------------
#define ALD 193

__global__ void attn_kernel() {
    extern __shared__ float sm[];
    float* qs = sm;
    float* ks = qs + CHUNK * ALD;
    float* vs = ks + CTX * ALD;
    float* rs = vs + CTX * ALD;
    float* sc = rs + PL * ALD;

    const int n = blockIdx.x;
    const int h = blockIdx.y;
    const int b = blockIdx.z;
    const int tid = threadIdx.x;

    const int base = b * SP + n * CHUNK;
    const size_t hoff = (size_t)h * HD;

    for (int e = tid; e < CHUNK * HD; e += 256) {
        int r = e / HD, d = e - r * HD;
        qs[r * ALD + d] = g_q[(size_t)(base + r) * HID + hoff + d];
    }
    for (int e = tid; e < CTX * HD; e += 256) {
        int r = e / HD, d = e - r * HD;
        int srow = base - MAX_PAST + r;
        float kk = 0.f, vv = 0.f;
        if (srow >= b * SP) {
            size_t off = (size_t)srow * HID + hoff + d;
            kk = g_k[off];
            vv = g_v[off];
        }
        ks[r * ALD + d] = kk;
        vs[r * ALD + d] = vv;
    }
    for (int e = tid; e < PL * HD; e += 256) {
        int p = e / HD, d = e - p * HD;
        rs[p * ALD + d] = g_rel[p * HID + hoff + d];
    }
    __syncthreads();

    for (int e = tid; e < CHUNK * CTX; e += 256) {
        int qi = e / CTX, c = e - qi * CTX;
        int absq = n * CHUNK + qi;
        int absk = n * CHUNK - MAX_PAST + c;
        bool valid = (absq < SEQ) && (absk >= 0) && (absk < SEQ) &&
                     (c > qi) && (c <= qi + MAX_PAST);
        float val = -1e9f;
        if (valid) {
            const float* qr = qs + qi * ALD;
            const float* kr = ks + c * ALD;
            const float* rr = rs + (c - qi) * ALD;
            float ac = 0.f, bd = 0.f;
#pragma unroll 8
            for (int d = 0; d < HD; d++) {
                float qv = qr[d];
                ac = fmaf(qv, kr[d], ac);
                bd = fmaf(qv, rr[d], bd);
            }
            float w = ac + bd;
            val = tanhf(w * (1.0f / SOFTCAP)) * SOFTCAP;
        }
        sc[e] = val;
    }
    __syncthreads();

    if (tid < CHUNK) {
        float* row = sc + tid * CTX;
        float mx = -1e30f;
#pragma unroll
        for (int c = 0; c < CTX; c++) mx = fmaxf(mx, row[c]);
        float s = 0.f;
#pragma unroll
        for (int c = 0; c < CTX; c++) {
            float e2 = __expf(row[c] - mx);
            row[c] = e2;
            s += e2;
        }
        float inv = 1.f / s;
#pragma unroll
        for (int c = 0; c < CTX; c++) row[c] *= inv;
    }
    __syncthreads();

    for (int e = tid; e < CHUNK * HD; e += 256) {
        int qi = e / HD, d = e - qi * HD;
        int absq = n * CHUNK + qi;
        if (absq >= SEQ) continue;
        const float* pr = sc + qi * CTX;
        float acc = 0.f;
#pragma unroll
        for (int c = 0; c < CTX; c++) acc = fmaf(pr[c], vs[c * ALD + d], acc);
        g_att[(size_t)(b * SEQ + absq) * HID + hoff + d] = acc;
    }
}

// ---------------- launch ----------------
extern "C" void kernel_launch(void* const* d_in, const int* in_sizes, int n_in,
                              void* d_out, int out_size) {
    const float* x     = (const float*)d_in[0];
    const float* pe    = (const float*)d_in[1];
    const float* Wq    = (const float*)d_in[2];
    const float* Wk    = (const float*)d_in[3];
    const float* Wv    = (const float*)d_in[4];
    const float* Wrel  = (const float*)d_in[5];
    const float* pds   = (const float*)d_in[6];
    const float* Wpost = (const float*)d_in[7];
    float* out = (float*)d_out;

    const int attn_smem =
        ((CHUNK + CTX + CTX + PL) * ALD + CHUNK * CTX) * (int)sizeof(float);
    cudaFuncSetAttribute(attn_kernel,
                         cudaFuncAttributeMaxDynamicSharedMemorySize, attn_smem);
    cudaFuncSetAttribute(tc_gemm<0>,
                         cudaFuncAttributeMaxDynamicSharedMemorySize, GSMEM);
    cudaFuncSetAttribute(tc_gemm<1>,
                         cudaFuncAttributeMaxDynamicSharedMemorySize, GSMEM);

    // order chosen so tc_gemm<0> sits in ncu's captured slot (4th launch)
    prep_qscale<<<1, 192>>>(pds);
    quant_rows<0><<<(MTOT + 7) / 8, 256>>>((const float4*)x);
    wquant<<<dim3(HID / 32, 4), dim3(32, 8)>>>(Wq, Wk, Wv, Wpost);

    tc_gemm<0><<<dim3(HID / BNT, MROUND / BMT, 3), GTHREADS, GSMEM>>>(nullptr);

    relgemm<<<HID / 128, 128>>>(pe, Wrel);
    attn_kernel<<<dim3(NB, NH, BATCH), 256, attn_smem>>>();
    quant_rows<1><<<(MTOT + 7) / 8, 256>>>(nullptr);

    tc_gemm<1><<<dim3(HID / BNT, MROUND / BMT, 1), GTHREADS, GSMEM>>>(out);
}